// round 1
// baseline (speedup 1.0000x reference)
#include <cuda_runtime.h>

#define DIM 16
#define NLAYERS 3
#define LSTEPS 10

typedef unsigned long long u64;

// ---- packed f32x2 helpers (Blackwell sm_103a) ----
__device__ __forceinline__ u64 pk2(float a, float b){
    u64 r; asm("mov.b64 %0, {%1, %2};" : "=l"(r) : "f"(a), "f"(b)); return r;
}
__device__ __forceinline__ void up2(u64 v, float& a, float& b){
    asm("mov.b64 {%0, %1}, %2;" : "=f"(a), "=f"(b) : "l"(v));
}
__device__ __forceinline__ u64 fma2(u64 a, u64 b, u64 c){
    u64 d; asm("fma.rn.f32x2 %0, %1, %2, %3;" : "=l"(d) : "l"(a), "l"(b), "l"(c)); return d;
}
__device__ __forceinline__ u64 add2(u64 a, u64 b){
    u64 d; asm("add.rn.f32x2 %0, %1, %2;" : "=l"(d) : "l"(a), "l"(b)); return d;
}
__device__ __forceinline__ u64 mul2(u64 a, u64 b){
    u64 d; asm("mul.rn.f32x2 %0, %1, %2;" : "=l"(d) : "l"(a), "l"(b)); return d;
}

// fast accurate-enough tanh: (e-1)/(e+1), e = 2^(2y*log2(e))
// MUFU ex2.approx + rcp.approx; absolute error ~few ulp (vs ~5e-4 for tanh.approx)
__device__ __forceinline__ float ftanh(float y){
    float z = fminf(y * 2.885390081777927f, 126.0f);  // 2*log2(e); clamp avoids inf*0=NaN
    float e; asm("ex2.approx.f32 %0, %1;" : "=f"(e) : "f"(z));
    float r; asm("rcp.approx.f32 %0, %1;" : "=f"(r) : "f"(e + 1.0f));
    return (e - 1.0f) * r;
}

#define ONE2_C  0x3F8000003F800000ULL
#define NONE2_C 0xBF800000BF800000ULL
#define HALF2_C 0x3F0000003F000000ULL

// s[j-pair] += sum_k x_k * M[k][j-pair]   (M in shared, broadcast LDS.128)
__device__ __forceinline__ void matvec_acc(const float* __restrict__ Msh,
                                           const float xv[16], u64 s[8]){
#pragma unroll
    for (int k = 0; k < 16; k++){
        u64 xk = pk2(xv[k], xv[k]);
        const ulonglong2* row = reinterpret_cast<const ulonglong2*>(Msh + k*16);
        ulonglong2 r0 = row[0], r1 = row[1], r2 = row[2], r3 = row[3];
        s[0] = fma2(xk, r0.x, s[0]); s[1] = fma2(xk, r0.y, s[1]);
        s[2] = fma2(xk, r1.x, s[2]); s[3] = fma2(xk, r1.y, s[3]);
        s[4] = fma2(xk, r2.x, s[4]); s[5] = fma2(xk, r2.y, s[5]);
        s[6] = fma2(xk, r3.x, s[6]); s[7] = fma2(xk, r3.y, s[7]);
    }
}

// f = (delta + x@M) * (1 - x^2)
__device__ __forceinline__ void forcev(const float* __restrict__ Msh,
                                       const float xv[16], const u64 dl[8], u64 f[8]){
    u64 s[8];
#pragma unroll
    for (int i = 0; i < 8; i++) s[i] = dl[i];
    matvec_acc(Msh, xv, s);
#pragma unroll
    for (int a = 0; a < 8; a++){
        u64 xp = pk2(xv[2*a], xv[2*a+1]);
        u64 u  = mul2(xp, xp);
        u64 w  = fma2(u, NONE2_C, ONE2_C);  // 1 - x^2
        f[a]   = mul2(s[a], w);
    }
}

__global__ void __launch_bounds__(256, 2)
ising_kernel(const float* __restrict__ Q, const float* __restrict__ delta,
             const float* __restrict__ y0, const float* __restrict__ vn,
             float* __restrict__ xout, float* __restrict__ energy, int B)
{
    __shared__ __align__(16) float Msh[DIM*DIM];
    int t = threadIdx.x;
    {
        int i = t >> 4, j = t & 15;
        if (t < 256){
            float v = 0.f;
            if (i != j){
                int a = i > j ? i : j, b = i > j ? j : i;
                v = Q[a*(a-1)/2 + b];
            }
            Msh[i*16 + j] = v;
        }
    }
    __syncthreads();

    int gid = blockIdx.x * blockDim.x + t;
    if (gid >= B) return;

    // delta packed into registers (uniform, L1-broadcast)
    u64 dl[8];
    {
        const ulonglong2* dp = reinterpret_cast<const ulonglong2*>(delta);
        ulonglong2 a = dp[0], b = dp[1], c = dp[2], d = dp[3];
        dl[0]=a.x; dl[1]=a.y; dl[2]=b.x; dl[3]=b.y;
        dl[4]=c.x; dl[5]=c.y; dl[6]=d.x; dl[7]=d.y;
    }

    // y0 row
    u64 yv[8];
    {
        const ulonglong2* yp = reinterpret_cast<const ulonglong2*>(y0 + (size_t)gid*16);
        ulonglong2 a = yp[0], b = yp[1], c = yp[2], d = yp[3];
        yv[0]=a.x; yv[1]=a.y; yv[2]=b.x; yv[3]=b.y;
        yv[4]=c.x; yv[5]=c.y; yv[6]=d.x; yv[7]=d.y;
    }

    float xv[16];
#pragma unroll
    for (int i = 0; i < 8; i++){
        float lo, hi; up2(yv[i], lo, hi);
        xv[2*i] = ftanh(lo); xv[2*i+1] = ftanh(hi);
    }

    // force carried across step AND layer boundaries (x unchanged there):
    // 31 force evals total instead of 60.
    u64 f[8];
    forcev(Msh, xv, dl, f);

#pragma unroll 1
    for (int l = 0; l < NLAYERS; l++){
        u64 vel[8];
        {
            const ulonglong2* vp =
                reinterpret_cast<const ulonglong2*>(vn + ((size_t)l * B + gid) * 16);
            ulonglong2 a = vp[0], b = vp[1], c = vp[2], d = vp[3];
            vel[0]=a.x; vel[1]=a.y; vel[2]=b.x; vel[3]=b.y;
            vel[4]=c.x; vel[5]=c.y; vel[6]=d.x; vel[7]=d.y;
        }
#pragma unroll 1
        for (int it = 0; it < LSTEPS; it++){
            u64 vh[8];
#pragma unroll
            for (int i = 0; i < 8; i++){
                vh[i] = fma2(f[i], HALF2_C, vel[i]);   // vel + 0.5*f
                yv[i] = add2(yv[i], vh[i]);            // y += vel_half
            }
            bool last = (l == NLAYERS-1) && (it == LSTEPS-1);
            if (!last){
#pragma unroll
                for (int i = 0; i < 8; i++){
                    float lo, hi; up2(yv[i], lo, hi);
                    xv[2*i] = ftanh(lo); xv[2*i+1] = ftanh(hi);
                }
                forcev(Msh, xv, dl, f);
#pragma unroll
                for (int i = 0; i < 8; i++)
                    vel[i] = fma2(f[i], HALF2_C, vh[i]);  // vel = vel_half + 0.5*f
            }
            // final step: only y matters (x_out = sign(y)); tanh/force/vel skipped
        }
    }

    // x_out = sign(y) with sign(0) -> -1
    float xo[16];
#pragma unroll
    for (int i = 0; i < 8; i++){
        float lo, hi; up2(yv[i], lo, hi);
        xo[2*i]   = lo > 0.f ? 1.f : -1.f;
        xo[2*i+1] = hi > 0.f ? 1.f : -1.f;
    }
    {
        float4* op = reinterpret_cast<float4*>(xout + (size_t)gid*16);
#pragma unroll
        for (int i = 0; i < 4; i++)
            op[i] = make_float4(xo[4*i], xo[4*i+1], xo[4*i+2], xo[4*i+3]);
    }

    // energy = sum_j (0.5*(x@M)_j + delta_j) * x_j
    u64 s[8];
#pragma unroll
    for (int i = 0; i < 8; i++) s[i] = 0ULL;
    matvec_acc(Msh, xo, s);
    u64 acc = 0ULL;
#pragma unroll
    for (int i = 0; i < 8; i++){
        u64 tj = fma2(s[i], HALF2_C, dl[i]);
        u64 xp = pk2(xo[2*i], xo[2*i+1]);
        acc = fma2(tj, xp, acc);
    }
    float elo, ehi; up2(acc, elo, ehi);
    energy[gid] = elo + ehi;
}

extern "C" void kernel_launch(void* const* d_in, const int* in_sizes, int n_in,
                              void* d_out, int out_size)
{
    // metadata order: inputs(B,1), Q(120), delta(16), y0(B,16), vel_noise(3,B,16)
    const float* Q     = (const float*)d_in[1];
    const float* delta = (const float*)d_in[2];
    const float* y0    = (const float*)d_in[3];
    const float* vn    = (const float*)d_in[4];
    int B = in_sizes[3] / 16;

    float* out    = (float*)d_out;
    float* xout   = out;                      // (B, 16)
    float* energy = out + (size_t)B * 16;     // (B,)

    int grid = (B + 255) / 256;
    ising_kernel<<<grid, 256>>>(Q, delta, y0, vn, xout, energy, B);
}